// round 16
// baseline (speedup 1.0000x reference)
#include <cuda_runtime.h>
#include <cuda_fp16.h>
#include <stdint.h>
#include <math.h>

#define D_MODEL 1536
#define S_LEN   4096
#define T_LEN   154
#define N_BC    8
#define N_B     2
#define N_H     24
#define DH      64

// ---------------- scratch (device globals; no allocation allowed) ----------------
__device__ __half g_HSh [N_BC * S_LEN * D_MODEL];
__device__ __half g_EHSh[N_BC * T_LEN * D_MODEL];
__device__ __half g_Qh  [N_BC * S_LEN * D_MODEL];
__device__ __half g_Kh  [N_BC * T_LEN * D_MODEL];
__device__ __half g_Vh  [N_BC * T_LEN * D_MODEL];
__device__ __half g_AOh [N_BC * S_LEN * D_MODEL];
__device__ __half g_Wqh[D_MODEL * D_MODEL];
__device__ __half g_Wkh[D_MODEL * D_MODEL];
__device__ __half g_Wvh[D_MODEL * D_MODEL];
__device__ __half g_Woh[D_MODEL * D_MODEL];

// ================= helpers =================
__device__ __forceinline__ uint32_t smem_u32(const void* p) {
    uint32_t a;
    asm("{ .reg .u64 t; cvta.to.shared.u64 t, %1; cvt.u32.u64 %0, t; }" : "=r"(a) : "l"(p));
    return a;
}
__device__ __forceinline__ void ldm_x4(uint32_t* r, uint32_t addr) {
    asm volatile("ldmatrix.sync.aligned.m8n8.x4.shared.b16 {%0,%1,%2,%3}, [%4];"
        : "=r"(r[0]), "=r"(r[1]), "=r"(r[2]), "=r"(r[3]) : "r"(addr));
}
__device__ __forceinline__ void ldm_x4_t(uint32_t* r, uint32_t addr) {
    asm volatile("ldmatrix.sync.aligned.m8n8.x4.trans.shared.b16 {%0,%1,%2,%3}, [%4];"
        : "=r"(r[0]), "=r"(r[1]), "=r"(r[2]), "=r"(r[3]) : "r"(addr));
}
__device__ __forceinline__ void mma16816h(float* d, const uint32_t* a,
                                          uint32_t b0, uint32_t b1) {
    asm volatile(
        "mma.sync.aligned.m16n8k16.row.col.f32.f16.f16.f32 "
        "{%0,%1,%2,%3}, {%4,%5,%6,%7}, {%8,%9}, {%0,%1,%2,%3};"
        : "+f"(d[0]), "+f"(d[1]), "+f"(d[2]), "+f"(d[3])
        : "r"(a[0]), "r"(a[1]), "r"(a[2]), "r"(a[3]), "r"(b0), "r"(b1));
}
__device__ __forceinline__ void cp_async16(uint32_t dst, const void* src) {
    asm volatile("cp.async.cg.shared.global [%0], [%1], 16;" :: "r"(dst), "l"(src));
}
#define CP_COMMIT() asm volatile("cp.async.commit_group;" ::: "memory")
#define CP_WAIT(n)  asm volatile("cp.async.wait_group %0;" :: "n"(n) : "memory")

__device__ __forceinline__ uint32_t packh2(float a, float b) {
    __half2 h = __floats2half2_rn(a, b);
    return *(uint32_t*)&h;
}
__device__ __forceinline__ float ex2a(float x) {
    float y; asm("ex2.approx.f32 %0, %1;" : "=f"(y) : "f"(x)); return y;
}
__device__ __forceinline__ float rcpa(float x) {
    float y; asm("rcp.approx.f32 %0, %1;" : "=f"(y) : "f"(x)); return y;
}

// ================= single fused fp32 -> fp16 convert (all 6 tensors) =================
#define N4_HS  (N_BC * S_LEN * D_MODEL / 4)
#define N4_EH  (N_BC * T_LEN * D_MODEL / 4)
#define N4_W   (D_MODEL * D_MODEL / 4)
#define F2H_TOTAL (N4_HS + N4_EH + 4 * N4_W)

__global__ void f2h_all(const float* __restrict__ HS,  const float* __restrict__ EHS,
                        const float* __restrict__ Wq,  const float* __restrict__ Wk,
                        const float* __restrict__ Wv,  const float* __restrict__ Wo,
                        __half* __restrict__ HSh, __half* __restrict__ EHSh,
                        __half* __restrict__ Wqh, __half* __restrict__ Wkh,
                        __half* __restrict__ Wvh, __half* __restrict__ Woh)
{
    int i = blockIdx.x * blockDim.x + threadIdx.x;
    if (i >= F2H_TOTAL) return;
    const float* x; __half* y; int off;
    if (i < N4_HS)                         { x = HS;  y = HSh;  off = i; }
    else if (i < N4_HS + N4_EH)            { x = EHS; y = EHSh; off = i - N4_HS; }
    else {
        int r = i - N4_HS - N4_EH;
        int w = r / N4_W; off = r - w * N4_W;
        switch (w) {
            case 0:  x = Wq; y = Wqh; break;
            case 1:  x = Wk; y = Wkh; break;
            case 2:  x = Wv; y = Wvh; break;
            default: x = Wo; y = Woh; break;
        }
    }
    float4 v = ((const float4*)x)[off];
    __half2* yp = (__half2*)y + off * 2;
    yp[0] = __floats2half2_rn(v.x, v.y);
    yp[1] = __floats2half2_rn(v.z, v.w);
}

// ================= fp16 GEMM core: 128x128 CTA, 256 thr, warp 32x64 ================
// BK=64, 3-stage cp.async, kk-phase staggered across warp parity.
#define LDA    72
#define ASTG   (128 * LDA)
#define STG2   (2 * ASTG)
#define NSTG   3
#define GEMM_SMEM_BYTES (NSTG * STG2 * 2)   // 110592

template<bool HOUT>
__device__ __forceinline__ void gemm_core(
    const __half* __restrict__ A, const __half* __restrict__ B,
    const float* __restrict__ bias, void* __restrict__ Yv,
    int M, int N, int K, int bm, int bn, char* smemc)
{
    const uint32_t sbase = smem_u32(smemc);
    const int tid  = threadIdx.x;
    const int wid  = tid >> 5;
    const int lane = tid & 31;
    const int wm   = wid & 3;
    const int wn   = wid >> 2;
    const int xrow = lane & 15;
    const int xk   = (lane >> 4) << 3;
    const int krot = (wid & 1) << 1;     // stagger: odd warps start at kk=2

    const int crow = tid >> 3;              // 0..31
    const int ccol = (tid & 7) << 3;
    const __half* aptr[4];
    const __half* bptr[4];
    uint32_t soff[4];
    #pragma unroll
    for (int t = 0; t < 4; ++t) {
        int row = crow + t * 32;
        aptr[t] = A + (size_t)min(bm + row, M - 1) * K + ccol;
        bptr[t] = B + (size_t)(bn + row) * K + ccol;
        soff[t] = (uint32_t)(row * LDA + ccol) * 2;
    }

    float acc[2][8][4];
    #pragma unroll
    for (int i = 0; i < 2; ++i)
        #pragma unroll
        for (int j = 0; j < 8; ++j)
            #pragma unroll
            for (int q = 0; q < 4; ++q) acc[i][j][q] = 0.f;

    const int NIT = K / 64;   // 24

    auto issue = [&](int it) {
        const int s  = it % NSTG;
        const int k0 = it * 64;
        uint32_t sa = sbase + (uint32_t)s * STG2 * 2;
        uint32_t sb = sa + ASTG * 2;
        #pragma unroll
        for (int t = 0; t < 4; ++t) {
            cp_async16(sa + soff[t], aptr[t] + k0);
            cp_async16(sb + soff[t], bptr[t] + k0);
        }
    };

    issue(0); CP_COMMIT();
    issue(1); CP_COMMIT();

    for (int it = 0; it < NIT; ++it) {
        if (it == NIT - 1) { CP_WAIT(0); } else { CP_WAIT(1); }
        __syncthreads();
        if (it + 2 < NIT) { issue(it + 2); CP_COMMIT(); }

        const uint32_t sa = sbase + (uint32_t)(it % NSTG) * STG2 * 2;
        const uint32_t sb = sa + ASTG * 2;

        #pragma unroll
        for (int kki = 0; kki < 4; ++kki) {
            const int kk = (kki + krot) & 3;      // phase-staggered across warps
            const int k0 = kk * 16;
            uint32_t af[2][4];
            #pragma unroll
            for (int mf = 0; mf < 2; ++mf)
                ldm_x4(af[mf], sa + (uint32_t)((wm * 32 + mf * 16 + xrow) * LDA + k0 + xk) * 2);
            uint32_t bf[4][4];
            #pragma unroll
            for (int nf4 = 0; nf4 < 4; ++nf4)
                ldm_x4(bf[nf4], sb + (uint32_t)((wn * 64 + nf4 * 16 + xrow) * LDA + k0 + xk) * 2);
            #pragma unroll
            for (int nf4 = 0; nf4 < 4; ++nf4) {
                #pragma unroll
                for (int mf = 0; mf < 2; ++mf) {
                    mma16816h(acc[mf][nf4 * 2],     af[mf], bf[nf4][0], bf[nf4][2]);
                    mma16816h(acc[mf][nf4 * 2 + 1], af[mf], bf[nf4][1], bf[nf4][3]);
                }
            }
        }
    }

    const int g  = lane >> 2;
    const int t2 = (lane & 3) << 1;
    #pragma unroll
    for (int mf = 0; mf < 2; ++mf) {
        int r0 = bm + wm * 32 + mf * 16 + g;
        #pragma unroll
        for (int nf = 0; nf < 8; ++nf) {
            int col = bn + wn * 64 + nf * 8 + t2;
            float bv0 = bias[col], bv1 = bias[col + 1];
            float v00 = acc[mf][nf][0] + bv0, v01 = acc[mf][nf][1] + bv1;
            float v10 = acc[mf][nf][2] + bv0, v11 = acc[mf][nf][3] + bv1;
            if (HOUT) {
                __half* Y = (__half*)Yv;
                if (r0 < M)     *(__half2*)(Y + (size_t)r0 * N + col)       = __floats2half2_rn(v00, v01);
                if (r0 + 8 < M) *(__half2*)(Y + (size_t)(r0 + 8) * N + col) = __floats2half2_rn(v10, v11);
            } else {
                float* Y = (float*)Yv;
                if (r0 < M)     *(float2*)(Y + (size_t)r0 * N + col)       = make_float2(v00, v01);
                if (r0 + 8 < M) *(float2*)(Y + (size_t)(r0 + 8) * N + col) = make_float2(v10, v11);
            }
        }
    }
}

#define QCTAS  3072
#define KVCTAS 120

__global__ __launch_bounds__(256, 2)
void qkv_gemm(const __half* __restrict__ HSh, const __half* __restrict__ EHSh,
              const __half* __restrict__ Wq, const float* __restrict__ bq, __half* __restrict__ Qh,
              const __half* __restrict__ Wk, const float* __restrict__ bk, __half* __restrict__ Kh,
              const __half* __restrict__ Wv, const float* __restrict__ bv, __half* __restrict__ Vh)
{
    extern __shared__ char smemc[];
    int id = blockIdx.x;
    const __half* A; const __half* B; const float* bias; __half* Y; int M, bm, bn;
    if (id < QCTAS) {
        A = HSh; B = Wq; bias = bq; Y = Qh; M = N_BC * S_LEN;
        bm = (id / 12) * 128; bn = (id % 12) * 128;
    } else if (id < QCTAS + KVCTAS) {
        int r = id - QCTAS;
        A = EHSh; B = Wk; bias = bk; Y = Kh; M = N_BC * T_LEN;
        bm = (r / 12) * 128; bn = (r % 12) * 128;
    } else {
        int r = id - QCTAS - KVCTAS;
        A = EHSh; B = Wv; bias = bv; Y = Vh; M = N_BC * T_LEN;
        bm = (r / 12) * 128; bn = (r % 12) * 128;
    }
    gemm_core<true>(A, B, bias, Y, M, D_MODEL, D_MODEL, bm, bn, smemc);
}

__global__ __launch_bounds__(256, 2)
void o_gemm(const __half* __restrict__ A, const __half* __restrict__ B,
            const float* __restrict__ bias, float* __restrict__ Y)
{
    extern __shared__ char smemc[];
    int id = blockIdx.x;
    gemm_core<false>(A, B, bias, Y, N_BC * S_LEN, D_MODEL, D_MODEL,
                     (id / 12) * 128, (id % 12) * 128, smemc);
}

// ================= register-softmax HMMA attention (s-tile 128) ====================
#define QST 72
#define KST 72
#define KV_MAT   (4 * 32 * KST * 2)
#define KV_STAGE (2 * KV_MAT)
#define ATTN_SMEM_BYTES (4 * 128 * QST * 2 + 2 * KV_STAGE)  // 147456

#define SM_SCALE 0.1803368801f

__global__ __launch_bounds__(256, 1)
void attn_reg(const __half* __restrict__ Q, const __half* __restrict__ K,
              const __half* __restrict__ V, __half* __restrict__ O)
{
    extern __shared__ char smemc[];
    __half* qb = (__half*)smemc;
    const uint32_t qbu = smem_u32(qb);
    const uint32_t kvu = qbu + 4 * 128 * QST * 2;

    const int tid  = threadIdx.x;
    const int wid  = tid >> 5;
    const int lane = tid & 31;
    const int b    = blockIdx.z;
    const int h    = blockIdx.y;
    const int s0   = blockIdx.x * 128;

    const int sbase = wid * 16;
    const int xrow  = lane & 15;
    const int xk    = (lane >> 4) << 3;
    const int g     = lane >> 2;
    const int q2    = (lane & 3) << 1;

    #pragma unroll
    for (int it = 0; it < 16; ++it) {
        int i  = tid + it * 256;
        int cc = i >> 10, r = i & 1023, si = r >> 3, d8 = (r & 7) << 3;
        const __half* gp = Q + ((size_t)(cc * N_B + b) * S_LEN + s0 + si) * D_MODEL + h * DH + d8;
        *(uint4*)(qb + (cc * 128 + si) * QST + d8) = *(const uint4*)gp;
    }

    const int NCH = (T_LEN + 31) / 32;

    auto issue = [&](int ch) {
        const int t0 = ch * 32;
        const uint32_t st = kvu + (uint32_t)(ch & 1) * KV_STAGE;
        #pragma unroll
        for (int it = 0; it < 4; ++it) {
            int i  = tid + it * 256;
            int cc = i >> 8, r = i & 255, tj = r >> 3, d8 = (r & 7) << 3;
            int t = min(t0 + tj, T_LEN - 1);
            size_t go = ((size_t)(cc * N_B + b) * T_LEN + t) * D_MODEL + h * DH + d8;
            uint32_t so = (uint32_t)((cc * 32 + tj) * KST + d8) * 2;
            cp_async16(st + so, K + go);
            cp_async16(st + KV_MAT + so, V + go);
        }
    };

    issue(0); CP_COMMIT();
    issue(1); CP_COMMIT();

    float oacc[4][8][4];
    #pragma unroll
    for (int c = 0; c < 4; ++c)
        #pragma unroll
        for (int j = 0; j < 8; ++j)
            #pragma unroll
            for (int e = 0; e < 4; ++e) oacc[c][j][e] = 0.f;
    float rsum[2][4];
    #pragma unroll
    for (int r = 0; r < 2; ++r)
        #pragma unroll
        for (int c = 0; c < 4; ++c) rsum[r][c] = 0.f;

    for (int ch = 0; ch < NCH; ++ch) {
        if (ch == NCH - 1) { CP_WAIT(0); } else { CP_WAIT(1); }
        __syncthreads();

        const uint32_t kbu = kvu + (uint32_t)(ch & 1) * KV_STAGE;
        const uint32_t vbu = kbu + KV_MAT;

        float sacc[4][4][4];
        #pragma unroll
        for (int c = 0; c < 4; ++c)
            #pragma unroll
            for (int j = 0; j < 4; ++j)
                #pragma unroll
                for (int e = 0; e < 4; ++e) sacc[c][j][e] = 0.f;

        #pragma unroll
        for (int c = 0; c < 4; ++c) {
            #pragma unroll
            for (int kk = 0; kk < 4; ++kk) {
                uint32_t af[4];
                ldm_x4(af, qbu + (uint32_t)((c * 128 + sbase + xrow) * QST + kk * 16 + xk) * 2);
                #pragma unroll
                for (int nf16 = 0; nf16 < 2; ++nf16) {
                    uint32_t bf[4];
                    ldm_x4(bf, kbu + (uint32_t)((c * 32 + nf16 * 16 + xrow) * KST + kk * 16 + xk) * 2);
                    mma16816h(sacc[c][nf16 * 2],     af, bf[0], bf[2]);
                    mma16816h(sacc[c][nf16 * 2 + 1], af, bf[1], bf[3]);
                }
            }
        }

        #pragma unroll
        for (int kk = 0; kk < 2; ++kk) {
            uint32_t wf[4][4];
            #pragma unroll
            for (int jh = 0; jh < 2; ++jh) {
                const int j = kk * 2 + jh;
                float wt[4][4];
                #pragma unroll
                for (int e = 0; e < 4; ++e) {
                    int col = ch * 32 + j * 8 + q2 + (e & 1);
                    float t3 = sacc[3][j][e] * SM_SCALE;
                    float e0 = ex2a(fmaf(sacc[0][j][e], SM_SCALE, -t3));
                    float e1 = ex2a(fmaf(sacc[1][j][e], SM_SCALE, -t3));
                    float e2 = ex2a(fmaf(sacc[2][j][e], SM_SCALE, -t3));
                    float inv = (col < T_LEN) ? rcpa(e0 + e1 + e2 + 1.f) : 0.f;
                    e0 *= inv; e1 *= inv; e2 *= inv;
                    int rr = e >> 1;
                    rsum[rr][0] += e0; rsum[rr][1] += e1;
                    rsum[rr][2] += e2; rsum[rr][3] += inv;
                    wt[0][e] = e0; wt[1][e] = e1; wt[2][e] = e2; wt[3][e] = inv;
                }
                #pragma unroll
                for (int c = 0; c < 4; ++c) {
                    wf[c][jh * 2 + 0] = packh2(wt[c][0], wt[c][1]);
                    wf[c][jh * 2 + 1] = packh2(wt[c][2], wt[c][3]);
                }
            }
            #pragma unroll
            for (int c = 0; c < 4; ++c) {
                #pragma unroll
                for (int nf16 = 0; nf16 < 4; ++nf16) {
                    uint32_t bf[4];
                    ldm_x4_t(bf, vbu + (uint32_t)((c * 32 + kk * 16 + xrow) * KST + nf16 * 16 + xk) * 2);
                    mma16816h(oacc[c][nf16 * 2],     wf[c], bf[0], bf[1]);
                    mma16816h(oacc[c][nf16 * 2 + 1], wf[c], bf[2], bf[3]);
                }
            }
        }
        __syncthreads();
        if (ch + 2 < NCH) { issue(ch + 2); CP_COMMIT(); }
    }

    #pragma unroll
    for (int x = 1; x <= 2; x <<= 1)
        #pragma unroll
        for (int r = 0; r < 2; ++r)
            #pragma unroll
            for (int c = 0; c < 4; ++c)
                rsum[r][c] += __shfl_xor_sync(0xffffffffu, rsum[r][c], x);

    #pragma unroll
    for (int c = 0; c < 4; ++c) {
        float inv0 = 1.f / (rsum[0][c] + 1e-8f);
        float inv1 = 1.f / (rsum[1][c] + 1e-8f);
        int row0 = s0 + sbase + g;
        __half* gp0 = O + ((size_t)(c * N_B + b) * S_LEN + row0) * D_MODEL + h * DH + q2;
        __half* gp1 = gp0 + (size_t)8 * D_MODEL;
        #pragma unroll
        for (int j = 0; j < 8; ++j) {
            *(__half2*)(gp0 + j * 8) = __floats2half2_rn(oacc[c][j][0] * inv0, oacc[c][j][1] * inv0);
            *(__half2*)(gp1 + j * 8) = __floats2half2_rn(oacc[c][j][2] * inv1, oacc[c][j][3] * inv1);
        }
    }
}

// ---------------- launch ----------------
extern "C" void kernel_launch(void* const* d_in, const int* in_sizes, int n_in,
                              void* d_out, int out_size)
{
    const float* HS  = (const float*)d_in[0];
    const float* EHS = (const float*)d_in[1];
    const float* Wq  = (const float*)d_in[2];
    const float* bq  = (const float*)d_in[3];
    const float* Wk  = (const float*)d_in[4];
    const float* bk  = (const float*)d_in[5];
    const float* Wv  = (const float*)d_in[6];
    const float* bv  = (const float*)d_in[7];
    const float* Wo  = (const float*)d_in[8];
    const float* bo  = (const float*)d_in[9];
    float* out = (float*)d_out;

    __half *pHSh, *pEHSh, *pQh, *pKh, *pVh, *pAOh, *pWqh, *pWkh, *pWvh, *pWoh;
    cudaGetSymbolAddress((void**)&pHSh,  g_HSh);
    cudaGetSymbolAddress((void**)&pEHSh, g_EHSh);
    cudaGetSymbolAddress((void**)&pQh,   g_Qh);
    cudaGetSymbolAddress((void**)&pKh,   g_Kh);
    cudaGetSymbolAddress((void**)&pVh,   g_Vh);
    cudaGetSymbolAddress((void**)&pAOh,  g_AOh);
    cudaGetSymbolAddress((void**)&pWqh,  g_Wqh);
    cudaGetSymbolAddress((void**)&pWkh,  g_Wkh);
    cudaGetSymbolAddress((void**)&pWvh,  g_Wvh);
    cudaGetSymbolAddress((void**)&pWoh,  g_Woh);

    cudaFuncSetAttribute(qkv_gemm, cudaFuncAttributeMaxDynamicSharedMemorySize, GEMM_SMEM_BYTES);
    cudaFuncSetAttribute(o_gemm,   cudaFuncAttributeMaxDynamicSharedMemorySize, GEMM_SMEM_BYTES);
    cudaFuncSetAttribute(attn_reg, cudaFuncAttributeMaxDynamicSharedMemorySize, ATTN_SMEM_BYTES);

    f2h_all<<<(F2H_TOTAL + 255) / 256, 256>>>(HS, EHS, Wq, Wk, Wv, Wo,
                                              pHSh, pEHSh, pWqh, pWkh, pWvh, pWoh);

    qkv_gemm<<<QCTAS + 2 * KVCTAS, 256, GEMM_SMEM_BYTES>>>(
        pHSh, pEHSh, pWqh, bq, pQh, pWkh, bk, pKh, pWvh, bv, pVh);
    attn_reg<<<dim3(S_LEN / 128, N_H, N_B), 256, ATTN_SMEM_BYTES>>>(pQh, pKh, pVh, pAOh);
    o_gemm<<<QCTAS, 256, GEMM_SMEM_BYTES>>>(pAOh, pWoh, bo, out);
}

// round 17
// speedup vs baseline: 1.0170x; 1.0170x over previous
#include <cuda_runtime.h>
#include <cuda_fp16.h>
#include <stdint.h>
#include <math.h>

#define D_MODEL 1536
#define S_LEN   4096
#define T_LEN   154
#define N_BC    8
#define N_B     2
#define N_H     24
#define DH      64

// ---------------- scratch (device globals; no allocation allowed) ----------------
__device__ __half g_HSh [N_BC * S_LEN * D_MODEL];
__device__ __half g_EHSh[N_BC * T_LEN * D_MODEL];
__device__ __half g_Qh  [N_BC * S_LEN * D_MODEL];
__device__ __half g_Kh  [N_BC * T_LEN * D_MODEL];
__device__ __half g_Vh  [N_BC * T_LEN * D_MODEL];
__device__ __half g_AOh [N_BC * S_LEN * D_MODEL];
__device__ __half g_Wqh[D_MODEL * D_MODEL];
__device__ __half g_Wkh[D_MODEL * D_MODEL];
__device__ __half g_Wvh[D_MODEL * D_MODEL];
__device__ __half g_Woh[D_MODEL * D_MODEL];

// ================= helpers =================
__device__ __forceinline__ uint32_t smem_u32(const void* p) {
    uint32_t a;
    asm("{ .reg .u64 t; cvta.to.shared.u64 t, %1; cvt.u32.u64 %0, t; }" : "=r"(a) : "l"(p));
    return a;
}
__device__ __forceinline__ void ldm_x4(uint32_t* r, uint32_t addr) {
    asm volatile("ldmatrix.sync.aligned.m8n8.x4.shared.b16 {%0,%1,%2,%3}, [%4];"
        : "=r"(r[0]), "=r"(r[1]), "=r"(r[2]), "=r"(r[3]) : "r"(addr));
}
__device__ __forceinline__ void ldm_x4_t(uint32_t* r, uint32_t addr) {
    asm volatile("ldmatrix.sync.aligned.m8n8.x4.trans.shared.b16 {%0,%1,%2,%3}, [%4];"
        : "=r"(r[0]), "=r"(r[1]), "=r"(r[2]), "=r"(r[3]) : "r"(addr));
}
__device__ __forceinline__ void mma16816h(float* d, const uint32_t* a,
                                          uint32_t b0, uint32_t b1) {
    asm volatile(
        "mma.sync.aligned.m16n8k16.row.col.f32.f16.f16.f32 "
        "{%0,%1,%2,%3}, {%4,%5,%6,%7}, {%8,%9}, {%0,%1,%2,%3};"
        : "+f"(d[0]), "+f"(d[1]), "+f"(d[2]), "+f"(d[3])
        : "r"(a[0]), "r"(a[1]), "r"(a[2]), "r"(a[3]), "r"(b0), "r"(b1));
}
__device__ __forceinline__ void cp_async16(uint32_t dst, const void* src) {
    asm volatile("cp.async.cg.shared.global [%0], [%1], 16;" :: "r"(dst), "l"(src));
}
#define CP_COMMIT() asm volatile("cp.async.commit_group;" ::: "memory")
#define CP_WAIT(n)  asm volatile("cp.async.wait_group %0;" :: "n"(n) : "memory")

__device__ __forceinline__ uint32_t packh2(float a, float b) {
    __half2 h = __floats2half2_rn(a, b);
    return *(uint32_t*)&h;
}
__device__ __forceinline__ float ex2a(float x) {
    float y; asm("ex2.approx.f32 %0, %1;" : "=f"(y) : "f"(x)); return y;
}
__device__ __forceinline__ float rcpa(float x) {
    float y; asm("rcp.approx.f32 %0, %1;" : "=f"(y) : "f"(x)); return y;
}

// ================= single fused fp32 -> fp16 convert (all 6 tensors) =================
#define N4_HS  (N_BC * S_LEN * D_MODEL / 4)
#define N4_EH  (N_BC * T_LEN * D_MODEL / 4)
#define N4_W   (D_MODEL * D_MODEL / 4)
#define F2H_TOTAL (N4_HS + N4_EH + 4 * N4_W)

__global__ void f2h_all(const float* __restrict__ HS,  const float* __restrict__ EHS,
                        const float* __restrict__ Wq,  const float* __restrict__ Wk,
                        const float* __restrict__ Wv,  const float* __restrict__ Wo,
                        __half* __restrict__ HSh, __half* __restrict__ EHSh,
                        __half* __restrict__ Wqh, __half* __restrict__ Wkh,
                        __half* __restrict__ Wvh, __half* __restrict__ Woh)
{
    int i = blockIdx.x * blockDim.x + threadIdx.x;
    if (i >= F2H_TOTAL) return;
    const float* x; __half* y; int off;
    if (i < N4_HS)                         { x = HS;  y = HSh;  off = i; }
    else if (i < N4_HS + N4_EH)            { x = EHS; y = EHSh; off = i - N4_HS; }
    else {
        int r = i - N4_HS - N4_EH;
        int w = r / N4_W; off = r - w * N4_W;
        switch (w) {
            case 0:  x = Wq; y = Wqh; break;
            case 1:  x = Wk; y = Wkh; break;
            case 2:  x = Wv; y = Wvh; break;
            default: x = Wo; y = Woh; break;
        }
    }
    float4 v = ((const float4*)x)[off];
    __half2* yp = (__half2*)y + off * 2;
    yp[0] = __floats2half2_rn(v.x, v.y);
    yp[1] = __floats2half2_rn(v.z, v.w);
}

// ================= fp16 GEMM core (R15 winner): 128x128 CTA, 256 thr, warp 32x64 ===
#define LDA    72
#define ASTG   (128 * LDA)
#define STG2   (2 * ASTG)
#define GEMM_SMEM_BYTES (2 * STG2 * 2)   // 73728

template<bool HOUT>
__device__ __forceinline__ void gemm_core(
    const __half* __restrict__ A, const __half* __restrict__ B,
    const float* __restrict__ bias, void* __restrict__ Yv,
    int M, int N, int K, int bm, int bn, char* smemc)
{
    const uint32_t sbase = smem_u32(smemc);
    const int tid  = threadIdx.x;
    const int wid  = tid >> 5;
    const int lane = tid & 31;
    const int wm   = wid & 3;
    const int wn   = wid >> 2;
    const int xrow = lane & 15;
    const int xk   = (lane >> 4) << 3;

    const int crow = tid >> 3;              // 0..31
    const int ccol = (tid & 7) << 3;
    const __half* aptr[4];
    const __half* bptr[4];
    uint32_t soff[4];
    #pragma unroll
    for (int t = 0; t < 4; ++t) {
        int row = crow + t * 32;
        aptr[t] = A + (size_t)min(bm + row, M - 1) * K + ccol;
        bptr[t] = B + (size_t)(bn + row) * K + ccol;
        soff[t] = (uint32_t)(row * LDA + ccol) * 2;
    }

    float acc[2][8][4];
    #pragma unroll
    for (int i = 0; i < 2; ++i)
        #pragma unroll
        for (int j = 0; j < 8; ++j)
            #pragma unroll
            for (int q = 0; q < 4; ++q) acc[i][j][q] = 0.f;

    const int NIT = K / 64;   // 24

    auto issue = [&](int it) {
        const int s  = it & 1;
        const int k0 = it * 64;
        uint32_t sa = sbase + (uint32_t)s * STG2 * 2;
        uint32_t sb = sa + ASTG * 2;
        #pragma unroll
        for (int t = 0; t < 4; ++t) {
            cp_async16(sa + soff[t], aptr[t] + k0);
            cp_async16(sb + soff[t], bptr[t] + k0);
        }
    };

    issue(0); CP_COMMIT();

    for (int it = 0; it < NIT; ++it) {
        CP_WAIT(0);
        __syncthreads();
        if (it + 1 < NIT) { issue(it + 1); CP_COMMIT(); }

        const uint32_t sa = sbase + (uint32_t)(it & 1) * STG2 * 2;
        const uint32_t sb = sa + ASTG * 2;

        #pragma unroll
        for (int kk = 0; kk < 4; ++kk) {
            const int k0 = kk * 16;
            uint32_t af[2][4];
            #pragma unroll
            for (int mf = 0; mf < 2; ++mf)
                ldm_x4(af[mf], sa + (uint32_t)((wm * 32 + mf * 16 + xrow) * LDA + k0 + xk) * 2);
            uint32_t bf[4][4];
            #pragma unroll
            for (int nf4 = 0; nf4 < 4; ++nf4)
                ldm_x4(bf[nf4], sb + (uint32_t)((wn * 64 + nf4 * 16 + xrow) * LDA + k0 + xk) * 2);
            #pragma unroll
            for (int nf4 = 0; nf4 < 4; ++nf4) {
                #pragma unroll
                for (int mf = 0; mf < 2; ++mf) {
                    mma16816h(acc[mf][nf4 * 2],     af[mf], bf[nf4][0], bf[nf4][2]);
                    mma16816h(acc[mf][nf4 * 2 + 1], af[mf], bf[nf4][1], bf[nf4][3]);
                }
            }
        }
    }

    const int g  = lane >> 2;
    const int t2 = (lane & 3) << 1;
    #pragma unroll
    for (int mf = 0; mf < 2; ++mf) {
        int r0 = bm + wm * 32 + mf * 16 + g;
        #pragma unroll
        for (int nf = 0; nf < 8; ++nf) {
            int col = bn + wn * 64 + nf * 8 + t2;
            float bv0 = bias[col], bv1 = bias[col + 1];
            float v00 = acc[mf][nf][0] + bv0, v01 = acc[mf][nf][1] + bv1;
            float v10 = acc[mf][nf][2] + bv0, v11 = acc[mf][nf][3] + bv1;
            if (HOUT) {
                __half* Y = (__half*)Yv;
                if (r0 < M)     *(__half2*)(Y + (size_t)r0 * N + col)       = __floats2half2_rn(v00, v01);
                if (r0 + 8 < M) *(__half2*)(Y + (size_t)(r0 + 8) * N + col) = __floats2half2_rn(v10, v11);
            } else {
                float* Y = (float*)Yv;
                if (r0 < M)     *(float2*)(Y + (size_t)r0 * N + col)       = make_float2(v00, v01);
                if (r0 + 8 < M) *(float2*)(Y + (size_t)(r0 + 8) * N + col) = make_float2(v10, v11);
            }
        }
    }
}

#define QCTAS  3072
#define KVCTAS 120

__global__ __launch_bounds__(256, 2)
void qkv_gemm(const __half* __restrict__ HSh, const __half* __restrict__ EHSh,
              const __half* __restrict__ Wq, const float* __restrict__ bq, __half* __restrict__ Qh,
              const __half* __restrict__ Wk, const float* __restrict__ bk, __half* __restrict__ Kh,
              const __half* __restrict__ Wv, const float* __restrict__ bv, __half* __restrict__ Vh)
{
    extern __shared__ char smemc[];
    int id = blockIdx.x;
    const __half* A; const __half* B; const float* bias; __half* Y; int M, bm, bn;
    if (id < QCTAS) {
        A = HSh; B = Wq; bias = bq; Y = Qh; M = N_BC * S_LEN;
        bm = (id / 12) * 128; bn = (id % 12) * 128;
    } else if (id < QCTAS + KVCTAS) {
        int r = id - QCTAS;
        A = EHSh; B = Wk; bias = bk; Y = Kh; M = N_BC * T_LEN;
        bm = (r / 12) * 128; bn = (r % 12) * 128;
    } else {
        int r = id - QCTAS - KVCTAS;
        A = EHSh; B = Wv; bias = bv; Y = Vh; M = N_BC * T_LEN;
        bm = (r / 12) * 128; bn = (r % 12) * 128;
    }
    gemm_core<true>(A, B, bias, Y, M, D_MODEL, D_MODEL, bm, bn, smemc);
}

__global__ __launch_bounds__(256, 2)
void o_gemm(const __half* __restrict__ A, const __half* __restrict__ B,
            const float* __restrict__ bias, float* __restrict__ Y)
{
    extern __shared__ char smemc[];
    int id = blockIdx.x;
    gemm_core<false>(A, B, bias, Y, N_BC * S_LEN, D_MODEL, D_MODEL,
                     (id / 12) * 128, (id % 12) * 128, smemc);
}

// ================= register-softmax HMMA attention (s-tile 128, async Q) ===========
#define QST 72
#define KST 72
#define KV_MAT   (4 * 32 * KST * 2)
#define KV_STAGE (2 * KV_MAT)
#define ATTN_SMEM_BYTES (4 * 128 * QST * 2 + 2 * KV_STAGE)  // 147456

#define SM_SCALE 0.1803368801f

__global__ __launch_bounds__(256, 1)
void attn_reg(const __half* __restrict__ Q, const __half* __restrict__ K,
              const __half* __restrict__ V, __half* __restrict__ O)
{
    extern __shared__ char smemc[];
    __half* qb = (__half*)smemc;
    const uint32_t qbu = smem_u32(qb);
    const uint32_t kvu = qbu + 4 * 128 * QST * 2;

    const int tid  = threadIdx.x;
    const int wid  = tid >> 5;
    const int lane = tid & 31;
    const int b    = blockIdx.z;
    const int h    = blockIdx.y;
    const int s0   = blockIdx.x * 128;

    const int sbase = wid * 16;
    const int xrow  = lane & 15;
    const int xk    = (lane >> 4) << 3;
    const int g     = lane >> 2;
    const int q2    = (lane & 3) << 1;

    // ---- Q tile via cp.async (group 0), overlapped with K/V prefetch ----
    #pragma unroll
    for (int it = 0; it < 16; ++it) {
        int i  = tid + it * 256;
        int cc = i >> 10, r = i & 1023, si = r >> 3, d8 = (r & 7) << 3;
        const __half* gp = Q + ((size_t)(cc * N_B + b) * S_LEN + s0 + si) * D_MODEL + h * DH + d8;
        cp_async16(qbu + (uint32_t)((cc * 128 + si) * QST + d8) * 2, gp);
    }
    CP_COMMIT();

    const int NCH = (T_LEN + 31) / 32;

    auto issue = [&](int ch) {
        const int t0 = ch * 32;
        const uint32_t st = kvu + (uint32_t)(ch & 1) * KV_STAGE;
        #pragma unroll
        for (int it = 0; it < 4; ++it) {
            int i  = tid + it * 256;
            int cc = i >> 8, r = i & 255, tj = r >> 3, d8 = (r & 7) << 3;
            int t = min(t0 + tj, T_LEN - 1);
            size_t go = ((size_t)(cc * N_B + b) * T_LEN + t) * D_MODEL + h * DH + d8;
            uint32_t so = (uint32_t)((cc * 32 + tj) * KST + d8) * 2;
            cp_async16(st + so, K + go);
            cp_async16(st + KV_MAT + so, V + go);
        }
    };

    issue(0); CP_COMMIT();
    issue(1); CP_COMMIT();

    float oacc[4][8][4];
    #pragma unroll
    for (int c = 0; c < 4; ++c)
        #pragma unroll
        for (int j = 0; j < 8; ++j)
            #pragma unroll
            for (int e = 0; e < 4; ++e) oacc[c][j][e] = 0.f;
    float rsum[2][4];
    #pragma unroll
    for (int r = 0; r < 2; ++r)
        #pragma unroll
        for (int c = 0; c < 4; ++c) rsum[r][c] = 0.f;

    for (int ch = 0; ch < NCH; ++ch) {
        // groups pending at ch=0: {Q, kv0, kv1} -> wait(1) drains Q + kv0
        if (ch == NCH - 1) { CP_WAIT(0); } else { CP_WAIT(1); }
        __syncthreads();

        const uint32_t kbu = kvu + (uint32_t)(ch & 1) * KV_STAGE;
        const uint32_t vbu = kbu + KV_MAT;

        float sacc[4][4][4];
        #pragma unroll
        for (int c = 0; c < 4; ++c)
            #pragma unroll
            for (int j = 0; j < 4; ++j)
                #pragma unroll
                for (int e = 0; e < 4; ++e) sacc[c][j][e] = 0.f;

        #pragma unroll
        for (int c = 0; c < 4; ++c) {
            #pragma unroll
            for (int kk = 0; kk < 4; ++kk) {
                uint32_t af[4];
                ldm_x4(af, qbu + (uint32_t)((c * 128 + sbase + xrow) * QST + kk * 16 + xk) * 2);
                #pragma unroll
                for (int nf16 = 0; nf16 < 2; ++nf16) {
                    uint32_t bf[4];
                    ldm_x4(bf, kbu + (uint32_t)((c * 32 + nf16 * 16 + xrow) * KST + kk * 16 + xk) * 2);
                    mma16816h(sacc[c][nf16 * 2],     af, bf[0], bf[2]);
                    mma16816h(sacc[c][nf16 * 2 + 1], af, bf[1], bf[3]);
                }
            }
        }

        #pragma unroll
        for (int kk = 0; kk < 2; ++kk) {
            uint32_t wf[4][4];
            #pragma unroll
            for (int jh = 0; jh < 2; ++jh) {
                const int j = kk * 2 + jh;
                float wt[4][4];
                #pragma unroll
                for (int e = 0; e < 4; ++e) {
                    int col = ch * 32 + j * 8 + q2 + (e & 1);
                    float t3 = sacc[3][j][e] * SM_SCALE;
                    float e0 = ex2a(fmaf(sacc[0][j][e], SM_SCALE, -t3));
                    float e1 = ex2a(fmaf(sacc[1][j][e], SM_SCALE, -t3));
                    float e2 = ex2a(fmaf(sacc[2][j][e], SM_SCALE, -t3));
                    float inv = (col < T_LEN) ? rcpa(e0 + e1 + e2 + 1.f) : 0.f;
                    e0 *= inv; e1 *= inv; e2 *= inv;
                    int rr = e >> 1;
                    rsum[rr][0] += e0; rsum[rr][1] += e1;
                    rsum[rr][2] += e2; rsum[rr][3] += inv;
                    wt[0][e] = e0; wt[1][e] = e1; wt[2][e] = e2; wt[3][e] = inv;
                }
                #pragma unroll
                for (int c = 0; c < 4; ++c) {
                    wf[c][jh * 2 + 0] = packh2(wt[c][0], wt[c][1]);
                    wf[c][jh * 2 + 1] = packh2(wt[c][2], wt[c][3]);
                }
            }
            #pragma unroll
            for (int c = 0; c < 4; ++c) {
                #pragma unroll
                for (int nf16 = 0; nf16 < 4; ++nf16) {
                    uint32_t bf[4];
                    ldm_x4_t(bf, vbu + (uint32_t)((c * 32 + kk * 16 + xrow) * KST + nf16 * 16 + xk) * 2);
                    mma16816h(oacc[c][nf16 * 2],     wf[c], bf[0], bf[1]);
                    mma16816h(oacc[c][nf16 * 2 + 1], wf[c], bf[2], bf[3]);
                }
            }
        }
        __syncthreads();
        if (ch + 2 < NCH) { issue(ch + 2); CP_COMMIT(); }
    }

    #pragma unroll
    for (int x = 1; x <= 2; x <<= 1)
        #pragma unroll
        for (int r = 0; r < 2; ++r)
            #pragma unroll
            for (int c = 0; c < 4; ++c)
                rsum[r][c] += __shfl_xor_sync(0xffffffffu, rsum[r][c], x);

    #pragma unroll
    for (int c = 0; c < 4; ++c) {
        float inv0 = 1.f / (rsum[0][c] + 1e-8f);
        float inv1 = 1.f / (rsum[1][c] + 1e-8f);
        int row0 = s0 + sbase + g;
        __half* gp0 = O + ((size_t)(c * N_B + b) * S_LEN + row0) * D_MODEL + h * DH + q2;
        __half* gp1 = gp0 + (size_t)8 * D_MODEL;
        #pragma unroll
        for (int j = 0; j < 8; ++j) {
            *(__half2*)(gp0 + j * 8) = __floats2half2_rn(oacc[c][j][0] * inv0, oacc[c][j][1] * inv0);
            *(__half2*)(gp1 + j * 8) = __floats2half2_rn(oacc[c][j][2] * inv1, oacc[c][j][3] * inv1);
        }
    }
}

// ---------------- launch ----------------
extern "C" void kernel_launch(void* const* d_in, const int* in_sizes, int n_in,
                              void* d_out, int out_size)
{
    const float* HS  = (const float*)d_in[0];
    const float* EHS = (const float*)d_in[1];
    const float* Wq  = (const float*)d_in[2];
    const float* bq  = (const float*)d_in[3];
    const float* Wk  = (const float*)d_in[4];
    const float* bk  = (const float*)d_in[5];
    const float* Wv  = (const float*)d_in[6];
    const float* bv  = (const float*)d_in[7];
    const float* Wo  = (const float*)d_in[8];
    const float* bo  = (const float*)d_in[9];
    float* out = (float*)d_out;

    __half *pHSh, *pEHSh, *pQh, *pKh, *pVh, *pAOh, *pWqh, *pWkh, *pWvh, *pWoh;
    cudaGetSymbolAddress((void**)&pHSh,  g_HSh);
    cudaGetSymbolAddress((void**)&pEHSh, g_EHSh);
    cudaGetSymbolAddress((void**)&pQh,   g_Qh);
    cudaGetSymbolAddress((void**)&pKh,   g_Kh);
    cudaGetSymbolAddress((void**)&pVh,   g_Vh);
    cudaGetSymbolAddress((void**)&pAOh,  g_AOh);
    cudaGetSymbolAddress((void**)&pWqh,  g_Wqh);
    cudaGetSymbolAddress((void**)&pWkh,  g_Wkh);
    cudaGetSymbolAddress((void**)&pWvh,  g_Wvh);
    cudaGetSymbolAddress((void**)&pWoh,  g_Woh);

    cudaFuncSetAttribute(qkv_gemm, cudaFuncAttributeMaxDynamicSharedMemorySize, GEMM_SMEM_BYTES);
    cudaFuncSetAttribute(o_gemm,   cudaFuncAttributeMaxDynamicSharedMemorySize, GEMM_SMEM_BYTES);
    cudaFuncSetAttribute(attn_reg, cudaFuncAttributeMaxDynamicSharedMemorySize, ATTN_SMEM_BYTES);

    f2h_all<<<(F2H_TOTAL + 255) / 256, 256>>>(HS, EHS, Wq, Wk, Wv, Wo,
                                              pHSh, pEHSh, pWqh, pWkh, pWvh, pWoh);

    qkv_gemm<<<QCTAS + 2 * KVCTAS, 256, GEMM_SMEM_BYTES>>>(
        pHSh, pEHSh, pWqh, bq, pQh, pWkh, bk, pKh, pWvh, bv, pVh);
    attn_reg<<<dim3(S_LEN / 128, N_H, N_B), 256, ATTN_SMEM_BYTES>>>(pQh, pKh, pVh, pAOh);
    o_gemm<<<QCTAS, 256, GEMM_SMEM_BYTES>>>(pAOh, pWoh, bo, out);
}